// round 1
// baseline (speedup 1.0000x reference)
#include <cuda_runtime.h>
#include <cuda_bf16.h>

// GRU: B=2048, T=256, F=64, H=32. Output = sigmoid(h_T @ W_head^T + b_head), [B,1] fp32.
//
// Strategy: 3 warps per batch row (one warp per gate r/z/n). CTA = 96 threads = 1 row.
//   - Lane j of warp g holds W_ih[g*32+j, 0:64] (64 regs) and W_hh[g*32+j, 0:32] (32 regs).
//   - Hidden state h replicated in all lanes' registers (32 regs); rebroadcast each step
//     through a 128-byte shared buffer with two __syncthreads.
//   - x_t read as 16 broadcast LDG.128 per warp (256B row; warps of same CTA hit L1).
// Steady-state per warp-step: 96 reg-reg FFMA + 16 LDG + ~12 LDS/STS + 2 BAR.

#define B_ 2048
#define T_ 256
#define F_ 64
#define H_ 32

__global__ __launch_bounds__(96, 4)
void tinyrnn_gru_kernel(const float* __restrict__ x,
                        const float* __restrict__ W_ih,
                        const float* __restrict__ W_hh,
                        const float* __restrict__ b_ih,
                        const float* __restrict__ b_hh,
                        const float* __restrict__ W_head,
                        const float* __restrict__ b_head,
                        float* __restrict__ out)
{
    const int b   = blockIdx.x;
    const int tid = threadIdx.x;
    const int g   = tid >> 5;   // 0 = r-gate warp, 1 = z-gate warp, 2 = n-gate warp
    const int j   = tid & 31;   // hidden unit owned by this lane

    __shared__ float sr[32];
    __shared__ float sz[32];
    __shared__ __align__(16) float sh[32];

    // ---- Load per-lane weights into registers ----
    const int row = g * 32 + j;            // row in the 3H x {F|H} weight matrices
    float Wx[64];
    float Wh[32];
    {
        const float4* p = reinterpret_cast<const float4*>(W_ih + row * F_);
        #pragma unroll
        for (int i = 0; i < 16; i++) {
            float4 v = p[i];
            Wx[4*i+0] = v.x; Wx[4*i+1] = v.y; Wx[4*i+2] = v.z; Wx[4*i+3] = v.w;
        }
        const float4* q = reinterpret_cast<const float4*>(W_hh + row * H_);
        #pragma unroll
        for (int i = 0; i < 8; i++) {
            float4 v = q[i];
            Wh[4*i+0] = v.x; Wh[4*i+1] = v.y; Wh[4*i+2] = v.z; Wh[4*i+3] = v.w;
        }
    }

    float bias, bias_h;
    if (g == 2) { bias = b_ih[row];              bias_h = b_hh[row]; }  // n: keep split (r multiplies h-part)
    else        { bias = b_ih[row] + b_hh[row];  bias_h = 0.f;       }

    // Replicated hidden state (all lanes hold full h) + this lane's own h_j
    float hrep[32];
    #pragma unroll
    for (int k = 0; k < 32; k++) hrep[k] = 0.f;
    float h_self = 0.f;

    const float4* xrow = reinterpret_cast<const float4*>(x + (size_t)b * (T_ * F_));

    for (int t = 0; t < T_; t++) {
        // ---- input projection: a = bias + sum_k x[k]*Wx[k]  (4 accumulators for ILP) ----
        const float4* xv = xrow + t * (F_ / 4);
        float a0 = bias, a1 = 0.f, a2 = 0.f, a3 = 0.f;
        #pragma unroll
        for (int c = 0; c < 16; c++) {
            float4 v = xv[c];
            a0 = fmaf(v.x, Wx[4*c+0], a0);
            a1 = fmaf(v.y, Wx[4*c+1], a1);
            a2 = fmaf(v.z, Wx[4*c+2], a2);
            a3 = fmaf(v.w, Wx[4*c+3], a3);
        }
        float a = (a0 + a1) + (a2 + a3);

        float ah = bias_h;
        if (g == 2) {
            // n-gate: recurrent part kept separate (gets multiplied by r)
            float b0 = ah, b1 = 0.f;
            #pragma unroll
            for (int k = 0; k < 32; k += 2) {
                b0 = fmaf(hrep[k+0], Wh[k+0], b0);
                b1 = fmaf(hrep[k+1], Wh[k+1], b1);
            }
            ah = b0 + b1;
        } else {
            float b0 = a, b1 = 0.f;
            #pragma unroll
            for (int k = 0; k < 32; k += 2) {
                b0 = fmaf(hrep[k+0], Wh[k+0], b0);
                b1 = fmaf(hrep[k+1], Wh[k+1], b1);
            }
            a = b0 + b1;
            float s = __fdividef(1.f, 1.f + __expf(-a));   // sigmoid
            if (g == 0) sr[j] = s; else sz[j] = s;
        }
        __syncthreads();

        if (g == 2) {
            float r = sr[j];
            float z = sz[j];
            float u = fmaf(r, ah, a);                 // xn + r*hn
            float e = __expf(-2.f * u);               // tanh(u) = (1-e)/(1+e)
            float n = __fdividef(1.f - e, 1.f + e);
            h_self  = fmaf(z, h_self - n, n);         // (1-z)*n + z*h
            sh[j]   = h_self;
        }
        __syncthreads();

        // ---- rebroadcast h to all lanes (8 uniform LDS.128) ----
        #pragma unroll
        for (int i = 0; i < 8; i++) {
            float4 hv = reinterpret_cast<const float4*>(sh)[i];
            hrep[4*i+0] = hv.x; hrep[4*i+1] = hv.y;
            hrep[4*i+2] = hv.z; hrep[4*i+3] = hv.w;
        }
    }

    // ---- head: y = sigmoid(h . W_head + b_head), warp 2 reduces ----
    if (g == 2) {
        float v = h_self * W_head[j];
        #pragma unroll
        for (int o = 16; o > 0; o >>= 1)
            v += __shfl_xor_sync(0xffffffffu, v, o);
        if (j == 0)
            out[b] = __fdividef(1.f, 1.f + __expf(-(v + b_head[0])));
    }
}

extern "C" void kernel_launch(void* const* d_in, const int* in_sizes, int n_in,
                              void* d_out, int out_size)
{
    const float* x      = (const float*)d_in[0];
    const float* W_ih   = (const float*)d_in[1];
    const float* W_hh   = (const float*)d_in[2];
    const float* b_ih   = (const float*)d_in[3];
    const float* b_hh   = (const float*)d_in[4];
    const float* W_head = (const float*)d_in[5];
    const float* b_head = (const float*)d_in[6];
    float* out = (float*)d_out;

    tinyrnn_gru_kernel<<<B_, 96>>>(x, W_ih, W_hh, b_ih, b_hh, W_head, b_head, out);
}

// round 2
// speedup vs baseline: 3.5894x; 3.5894x over previous
#include <cuda_runtime.h>
#include <cuda_bf16.h>

// GRU B=2048, T=256, F=64, H=32; out = sigmoid(h_T . W_head + b_head), [B,1] fp32.
//
// Two-phase:
//  Phase 1 (proj_kernel): xg[bt][g] = b_ih[g] + sum_k x[bt][k] * W_ih[g][k]
//    - 96 threads/CTA, lane owns output g; weights (64 fp32) in registers.
//    - 128 x-rows staged in smem per CTA; read as uniform broadcast LDS.128.
//    - Stores coalesced (lane j -> xg[row*96 + g]).
//  Phase 2 (gru_kernel): warp per batch row; lane j owns hidden unit j with
//    W_hh rows (j, 32+j, 64+j) in registers (96 fp32). h rebroadcast via a
//    per-warp double-buffered 32-float smem line + one __syncwarp per step.
//    xg loads software-pipelined one step ahead. No CTA barriers anywhere.

#define B_ 2048
#define T_ 256
#define F_ 64
#define H_ 32
#define G_ 96   // 3*H

// scratch for xg: [B*T][96] fp32 = 201 MB
__device__ float g_xg[(size_t)B_ * T_ * G_];

__device__ __forceinline__ float tanh_fast(float v) {
    float y;
    asm("tanh.approx.f32 %0, %1;" : "=f"(y) : "f"(v));
    return y;
}
__device__ __forceinline__ float sigmoid_fast(float a) {
    return fmaf(tanh_fast(0.5f * a), 0.5f, 0.5f);
}

// ---------------- Phase 1: input projection ----------------
#define ROWS_P1 128

__global__ __launch_bounds__(96, 7)
void proj_kernel(const float* __restrict__ x,
                 const float* __restrict__ W_ih,
                 const float* __restrict__ b_ih,
                 float* __restrict__ xg)
{
    __shared__ __align__(16) float xs[ROWS_P1][F_];

    const int tid = threadIdx.x;
    const int g   = tid;                       // 96 threads = 96 outputs
    const size_t base = (size_t)blockIdx.x * ROWS_P1;

    // stage x tile [128 x 64] coalesced
    {
        const float4* xin = reinterpret_cast<const float4*>(x + base * F_);
        float4* xs4 = reinterpret_cast<float4*>(&xs[0][0]);
        #pragma unroll
        for (int i = 0; i < (ROWS_P1 * F_ / 4 + 95) / 96; i++) {
            int idx = tid + i * 96;
            if (idx < ROWS_P1 * F_ / 4) xs4[idx] = xin[idx];
        }
    }

    // per-lane weight row (one-time, L2-cached across CTAs)
    float W[F_];
    {
        const float4* wp = reinterpret_cast<const float4*>(W_ih + g * F_);
        #pragma unroll
        for (int i = 0; i < F_ / 4; i++) {
            float4 v = wp[i];
            W[4*i+0] = v.x; W[4*i+1] = v.y; W[4*i+2] = v.z; W[4*i+3] = v.w;
        }
    }
    const float bias = b_ih[g];
    __syncthreads();

    float* outp = xg + base * G_ + g;
    #pragma unroll 1
    for (int r = 0; r < ROWS_P1; r += 2) {
        const float4* x0 = reinterpret_cast<const float4*>(xs[r]);
        const float4* x1 = reinterpret_cast<const float4*>(xs[r + 1]);
        float a0 = bias, a1 = 0.f, b0 = bias, b1 = 0.f;
        #pragma unroll
        for (int c = 0; c < F_ / 4; c++) {
            float4 u = x0[c];
            float4 v = x1[c];
            a0 = fmaf(u.x, W[4*c+0], a0);
            a1 = fmaf(u.y, W[4*c+1], a1);
            a0 = fmaf(u.z, W[4*c+2], a0);
            a1 = fmaf(u.w, W[4*c+3], a1);
            b0 = fmaf(v.x, W[4*c+0], b0);
            b1 = fmaf(v.y, W[4*c+1], b1);
            b0 = fmaf(v.z, W[4*c+2], b0);
            b1 = fmaf(v.w, W[4*c+3], b1);
        }
        outp[(size_t)r * G_]       = a0 + a1;
        outp[(size_t)(r + 1) * G_] = b0 + b1;
    }
}

// ---------------- Phase 2: recurrence ----------------
#define WARPS_P2 4

__global__ __launch_bounds__(32 * WARPS_P2, 4)
void gru_kernel(const float* __restrict__ xg,
                const float* __restrict__ W_hh,
                const float* __restrict__ b_hh,
                const float* __restrict__ W_head,
                const float* __restrict__ b_head,
                float* __restrict__ out)
{
    __shared__ __align__(16) float sh[WARPS_P2][2][H_];

    const int wid = threadIdx.x >> 5;
    const int j   = threadIdx.x & 31;
    const int row = blockIdx.x * WARPS_P2 + wid;   // batch index

    // per-lane recurrent weights: rows j (r), 32+j (z), 64+j (n)
    float Wr[H_], Wz[H_], Wn[H_];
    {
        const float4* pr = reinterpret_cast<const float4*>(W_hh + (j)        * H_);
        const float4* pz = reinterpret_cast<const float4*>(W_hh + (H_ + j)   * H_);
        const float4* pn = reinterpret_cast<const float4*>(W_hh + (2*H_ + j) * H_);
        #pragma unroll
        for (int i = 0; i < H_ / 4; i++) {
            float4 a = pr[i], b = pz[i], c = pn[i];
            Wr[4*i+0]=a.x; Wr[4*i+1]=a.y; Wr[4*i+2]=a.z; Wr[4*i+3]=a.w;
            Wz[4*i+0]=b.x; Wz[4*i+1]=b.y; Wz[4*i+2]=b.z; Wz[4*i+3]=b.w;
            Wn[4*i+0]=c.x; Wn[4*i+1]=c.y; Wn[4*i+2]=c.z; Wn[4*i+3]=c.w;
        }
    }
    const float br = b_hh[j];
    const float bz = b_hh[H_ + j];
    const float bn = b_hh[2*H_ + j];

    const float* xp = xg + (size_t)row * T_ * G_;

    // init h = 0
    sh[wid][0][j] = 0.f;
    float h = 0.f;
    __syncwarp();

    // prefetch t=0 gates
    float xr = xp[j], xz = xp[H_ + j], xn = xp[2*H_ + j];

    #pragma unroll 1
    for (int t = 0; t < T_; t++) {
        // software-prefetch next step's xg
        float nxr = 0.f, nxz = 0.f, nxn = 0.f;
        if (t + 1 < T_) {
            const float* xq = xp + (size_t)(t + 1) * G_;
            nxr = xq[j]; nxz = xq[H_ + j]; nxn = xq[2*H_ + j];
        }

        // recurrent dot products (h broadcast from smem, weights in regs)
        const float4* hp = reinterpret_cast<const float4*>(sh[wid][t & 1]);
        float ar = br, ar2 = 0.f;
        float az = bz, az2 = 0.f;
        float an = bn, an2 = 0.f;
        #pragma unroll
        for (int i = 0; i < H_ / 4; i++) {
            float4 hv = hp[i];
            ar  = fmaf(hv.x, Wr[4*i+0], ar);
            ar2 = fmaf(hv.y, Wr[4*i+1], ar2);
            az  = fmaf(hv.x, Wz[4*i+0], az);
            az2 = fmaf(hv.y, Wz[4*i+1], az2);
            an  = fmaf(hv.x, Wn[4*i+0], an);
            an2 = fmaf(hv.y, Wn[4*i+1], an2);
            ar  = fmaf(hv.z, Wr[4*i+2], ar);
            ar2 = fmaf(hv.w, Wr[4*i+3], ar2);
            az  = fmaf(hv.z, Wz[4*i+2], az);
            az2 = fmaf(hv.w, Wz[4*i+3], az2);
            an  = fmaf(hv.z, Wn[4*i+2], an);
            an2 = fmaf(hv.w, Wn[4*i+3], an2);
        }

        float r = sigmoid_fast(xr + (ar + ar2));
        float z = sigmoid_fast(xz + (az + az2));
        float n = tanh_fast(fmaf(r, an + an2, xn));
        h = fmaf(z, h - n, n);

        sh[wid][(t + 1) & 1][j] = h;
        __syncwarp();

        xr = nxr; xz = nxz; xn = nxn;
    }

    // head: sigmoid(h . W_head + b_head)
    float v = h * W_head[j];
    #pragma unroll
    for (int o = 16; o > 0; o >>= 1)
        v += __shfl_xor_sync(0xffffffffu, v, o);
    if (j == 0)
        out[row] = sigmoid_fast(v + b_head[0]);
}

extern "C" void kernel_launch(void* const* d_in, const int* in_sizes, int n_in,
                              void* d_out, int out_size)
{
    const float* x      = (const float*)d_in[0];
    const float* W_ih   = (const float*)d_in[1];
    const float* W_hh   = (const float*)d_in[2];
    const float* b_ih   = (const float*)d_in[3];
    const float* b_hh   = (const float*)d_in[4];
    const float* W_head = (const float*)d_in[5];
    const float* b_head = (const float*)d_in[6];
    float* out = (float*)d_out;

    float* xg;
    cudaGetSymbolAddress((void**)&xg, g_xg);

    proj_kernel<<<(B_ * T_) / ROWS_P1, 96>>>(x, W_ih, b_ih, xg);
    gru_kernel<<<B_ / WARPS_P2, 32 * WARPS_P2>>>(xg, W_hh, b_hh, W_head, b_head, out);
}

// round 10
// speedup vs baseline: 7.3581x; 2.0500x over previous
#include <cuda_runtime.h>
#include <cuda_bf16.h>
#include <cstdint>

#define B_ 2048
#define T_ 256
#define F_ 64
#define H_ 32
#define G_ 96

// scratch: xg[B*T][96] fp32 (201 MB)
__device__ float g_xg[(size_t)B_ * T_ * G_];

__device__ __forceinline__ uint32_t smem_u32(const void* p) {
    uint32_t a;
    asm("{ .reg .u64 t; cvta.to.shared.u64 t, %1; cvt.u32.u64 %0, t; }" : "=r"(a) : "l"(p));
    return a;
}
__device__ __forceinline__ float tanh_fast(float v) {
    float y; asm("tanh.approx.f32 %0, %1;" : "=f"(y) : "f"(v)); return y;
}
__device__ __forceinline__ float sigmoid_fast(float a) {
    return fmaf(tanh_fast(0.5f * a), 0.5f, 0.5f);
}
__device__ __forceinline__ uint64_t ffma2(uint64_t a, uint64_t b, uint64_t c) {
    uint64_t d;
    asm("fma.rn.f32x2 %0, %1, %2, %3;" : "=l"(d) : "l"(a), "l"(b), "l"(c));
    return d;
}
__device__ __forceinline__ uint32_t pack_bf16(float a, float b) {
    __nv_bfloat162 t = __floats2bfloat162_rn(a, b);   // .x = a in low 16 bits
    return *reinterpret_cast<uint32_t*>(&t);
}

// ================= Phase 1: xg = x @ W_ih^T + b_ih  (mma.sync bf16, 3-pass split) ===========
// CTA: 256 threads (8 warps). Tile M=128 (rows), N=96 (gates), K=64.
// Warp w computes rows [16w, 16w+16) x all 96 cols via 12 n-tiles of m16n8k16.

#define PM 128
#define AROW 144                 // padded A row: 72 bf16 = 144B (conflict-free frags)
#define AH_OFF 0
#define AL_OFF (PM * AROW)                 // 18432
#define BH_OFF (2 * PM * AROW)             // 36864
#define BL_OFF (BH_OFF + G_ * AROW)        // 50688
#define SMEM_P1 (BL_OFF + G_ * AROW)       // 64512
#define STRIDE_ST 100            // stage stride (floats)

__device__ __forceinline__ void mma_bf16(float* d, uint32_t a0, uint32_t a1, uint32_t a2,
                                         uint32_t a3, uint32_t b0, uint32_t b1) {
    asm("mma.sync.aligned.m16n8k16.row.col.f32.bf16.bf16.f32 "
        "{%0,%1,%2,%3}, {%4,%5,%6,%7}, {%8,%9}, {%0,%1,%2,%3};"
        : "+f"(d[0]), "+f"(d[1]), "+f"(d[2]), "+f"(d[3])
        : "r"(a0), "r"(a1), "r"(a2), "r"(a3), "r"(b0), "r"(b1));
}

// convert float4 -> hi uint2 / lo uint2 (bf16 pairs, low half = even element)
__device__ __forceinline__ void split4(float4 v, uint2& hp, uint2& lp) {
    __nv_bfloat16 h0 = __float2bfloat16(v.x), h1 = __float2bfloat16(v.y);
    __nv_bfloat16 h2 = __float2bfloat16(v.z), h3 = __float2bfloat16(v.w);
    hp.x = pack_bf16(__bfloat162float(h0), __bfloat162float(h1));
    hp.y = pack_bf16(__bfloat162float(h2), __bfloat162float(h3));
    lp.x = pack_bf16(v.x - __bfloat162float(h0), v.y - __bfloat162float(h1));
    lp.y = pack_bf16(v.z - __bfloat162float(h2), v.w - __bfloat162float(h3));
}

__global__ __launch_bounds__(256, 3)
void proj_kernel(const float* __restrict__ x,
                 const float* __restrict__ W_ih,
                 const float* __restrict__ b_ih,
                 float* __restrict__ xg)
{
    extern __shared__ __align__(16) char dsm[];
    __shared__ __align__(16) float sbias[G_];

    const int tid  = threadIdx.x;
    const int wid  = tid >> 5;
    const int lane = tid & 31;
    const int g    = lane >> 2;      // fragment group (row / col index 0..7)
    const int tg   = lane & 3;       // thread-in-group
    const size_t base = (size_t)blockIdx.x * PM;

    // ---- stage A = x tile [128 x 64] -> bf16 hi/lo ----
    {
        const float4* xin = reinterpret_cast<const float4*>(x + base * F_);
        #pragma unroll
        for (int it = 0; it < PM * F_ / 4 / 256; it++) {
            int i = tid + it * 256;
            float4 v = xin[i];
            int row = i >> 4, c4 = i & 15;
            uint2 hp, lp; split4(v, hp, lp);
            uint32_t off = row * AROW + c4 * 8;
            *reinterpret_cast<uint2*>(dsm + AH_OFF + off) = hp;
            *reinterpret_cast<uint2*>(dsm + AL_OFF + off) = lp;
        }
    }
    // ---- stage B = W_ih [96 x 64] -> bf16 hi/lo ----
    {
        const float4* win = reinterpret_cast<const float4*>(W_ih);
        #pragma unroll
        for (int it = 0; it < G_ * F_ / 4 / 256; it++) {
            int i = tid + it * 256;
            float4 v = win[i];
            int row = i >> 4, c4 = i & 15;
            uint2 hp, lp; split4(v, hp, lp);
            uint32_t off = row * AROW + c4 * 8;
            *reinterpret_cast<uint2*>(dsm + BH_OFF + off) = hp;
            *reinterpret_cast<uint2*>(dsm + BL_OFF + off) = lp;
        }
    }
    if (tid < G_) sbias[tid] = b_ih[tid];
    __syncthreads();

    // ---- mma compute: warp owns rows m0..m0+15 ----
    const int m0 = wid * 16;
    float acc[12][4];
    #pragma unroll
    for (int n = 0; n < 12; n++)
        #pragma unroll
        for (int q = 0; q < 4; q++) acc[n][q] = 0.f;

    const uint32_t arow0 = (m0 + g) * AROW;
    const uint32_t arow1 = (m0 + g + 8) * AROW;

    #pragma unroll
    for (int k = 0; k < 4; k++) {
        const uint32_t c0 = (k * 16 + 2 * tg) * 2;       // bytes
        const uint32_t c1 = c0 + 16;                      // +8 cols
        uint32_t ah0 = *reinterpret_cast<const uint32_t*>(dsm + AH_OFF + arow0 + c0);
        uint32_t ah1 = *reinterpret_cast<const uint32_t*>(dsm + AH_OFF + arow1 + c0);
        uint32_t ah2 = *reinterpret_cast<const uint32_t*>(dsm + AH_OFF + arow0 + c1);
        uint32_t ah3 = *reinterpret_cast<const uint32_t*>(dsm + AH_OFF + arow1 + c1);
        uint32_t al0 = *reinterpret_cast<const uint32_t*>(dsm + AL_OFF + arow0 + c0);
        uint32_t al1 = *reinterpret_cast<const uint32_t*>(dsm + AL_OFF + arow1 + c0);
        uint32_t al2 = *reinterpret_cast<const uint32_t*>(dsm + AL_OFF + arow0 + c1);
        uint32_t al3 = *reinterpret_cast<const uint32_t*>(dsm + AL_OFF + arow1 + c1);
        #pragma unroll
        for (int n = 0; n < 12; n++) {
            const uint32_t brow = (n * 8 + g) * AROW;
            uint32_t bh0 = *reinterpret_cast<const uint32_t*>(dsm + BH_OFF + brow + c0);
            uint32_t bh1 = *reinterpret_cast<const uint32_t*>(dsm + BH_OFF + brow + c1);
            uint32_t bl0 = *reinterpret_cast<const uint32_t*>(dsm + BL_OFF + brow + c0);
            uint32_t bl1 = *reinterpret_cast<const uint32_t*>(dsm + BL_OFF + brow + c1);
            mma_bf16(acc[n], ah0, ah1, ah2, ah3, bh0, bh1);
            mma_bf16(acc[n], ah0, ah1, ah2, ah3, bl0, bl1);
            mma_bf16(acc[n], al0, al1, al2, al3, bh0, bh1);
        }
    }
    __syncthreads();   // done reading A/B smem; reuse as stage

    // ---- stage results (smem, padded rows) ----
    float* stage = reinterpret_cast<float*>(dsm);
    {
        #pragma unroll
        for (int n = 0; n < 12; n++) {
            int c = n * 8 + 2 * tg;
            float2* p0 = reinterpret_cast<float2*>(&stage[(m0 + g) * STRIDE_ST + c]);
            float2* p1 = reinterpret_cast<float2*>(&stage[(m0 + g + 8) * STRIDE_ST + c]);
            *p0 = make_float2(acc[n][0], acc[n][1]);
            *p1 = make_float2(acc[n][2], acc[n][3]);
        }
    }
    __syncthreads();

    // ---- coalesced store with bias add ----
    {
        float4* outp = reinterpret_cast<float4*>(xg + base * G_);
        #pragma unroll
        for (int it = 0; it < PM * G_ / 4 / 256; it++) {
            int i = tid + it * 256;
            int e = 4 * i;
            int r = e / G_, c = e % G_;
            float4 bb = *reinterpret_cast<const float4*>(&sbias[c]);
            const float* sp = &stage[r * STRIDE_ST + c];
            float4 v;
            v.x = sp[0] + bb.x; v.y = sp[1] + bb.y;
            v.z = sp[2] + bb.z; v.w = sp[3] + bb.w;
            outp[i] = v;
        }
    }
}

// ================= Phase 2: recurrence (warp/row, cp.async ring, f32x2 FMA) =================
#define WARPS_P2 4
#define PF 7

__global__ __launch_bounds__(32 * WARPS_P2, 4)
void gru_kernel(const float* __restrict__ xg,
                const float* __restrict__ W_hh,
                const float* __restrict__ b_hh,
                const float* __restrict__ W_head,
                const float* __restrict__ b_head,
                float* __restrict__ out)
{
    __shared__ __align__(16) float ring[WARPS_P2][8][G_];
    __shared__ __align__(16) float sh[WARPS_P2][2][H_];

    const int wid = threadIdx.x >> 5;
    const int j   = threadIdx.x & 31;
    const int row = blockIdx.x * WARPS_P2 + wid;

    // per-lane recurrent weights, packed as f32x2 pairs (low = even index)
    uint64_t Wr2[H_ / 2], Wz2[H_ / 2], Wn2[H_ / 2];
    {
        const ulonglong2* pr = reinterpret_cast<const ulonglong2*>(W_hh + (j)          * H_);
        const ulonglong2* pz = reinterpret_cast<const ulonglong2*>(W_hh + (H_ + j)     * H_);
        const ulonglong2* pn = reinterpret_cast<const ulonglong2*>(W_hh + (2 * H_ + j) * H_);
        #pragma unroll
        for (int i = 0; i < H_ / 4; i++) {
            ulonglong2 a = pr[i], b = pz[i], c = pn[i];
            Wr2[2*i] = a.x; Wr2[2*i+1] = a.y;
            Wz2[2*i] = b.x; Wz2[2*i+1] = b.y;
            Wn2[2*i] = c.x; Wn2[2*i+1] = c.y;
        }
    }
    const uint64_t br2 = (uint64_t)__float_as_uint(b_hh[j]);          // (b, 0)
    const uint64_t bz2 = (uint64_t)__float_as_uint(b_hh[H_ + j]);
    const uint64_t bn2 = (uint64_t)__float_as_uint(b_hh[2 * H_ + j]);

    const float* xp = xg + (size_t)row * T_ * G_;
    const uint32_t rb = smem_u32(&ring[wid][0][0]);

    #pragma unroll
    for (int p = 0; p < PF; p++) {
        if (j < 24) {
            uint32_t dst = rb + (uint32_t)p * (G_ * 4) + j * 16;
            const float* src = xp + p * G_ + j * 4;
            asm volatile("cp.async.cg.shared.global [%0], [%1], 16;" :: "r"(dst), "l"(src));
        }
        asm volatile("cp.async.commit_group;" ::: "memory");
    }

    sh[wid][0][j] = 0.f;
    float h = 0.f;
    __syncwarp();

    #pragma unroll 1
    for (int t = 0; t < T_; t++) {
        {
            int ft = t + PF;
            if (ft < T_ && j < 24) {
                uint32_t dst = rb + (uint32_t)(ft & 7) * (G_ * 4) + j * 16;
                const float* src = xp + (size_t)ft * G_ + j * 4;
                asm volatile("cp.async.cg.shared.global [%0], [%1], 16;" :: "r"(dst), "l"(src));
            }
            asm volatile("cp.async.commit_group;" ::: "memory");
            asm volatile("cp.async.wait_group 6;" ::: "memory");
            __syncwarp();
        }

        const float* xs = &ring[wid][t & 7][0];
        float xr = xs[j], xz = xs[H_ + j], xn = xs[2 * H_ + j];

        const ulonglong2* hp = reinterpret_cast<const ulonglong2*>(sh[wid][t & 1]);
        uint64_t ar = br2, az = bz2, an = bn2;
        #pragma unroll
        for (int i = 0; i < H_ / 4; i++) {
            ulonglong2 hv = hp[i];
            ar = ffma2(hv.x, Wr2[2*i],   ar);
            az = ffma2(hv.x, Wz2[2*i],   az);
            an = ffma2(hv.x, Wn2[2*i],   an);
            ar = ffma2(hv.y, Wr2[2*i+1], ar);
            az = ffma2(hv.y, Wz2[2*i+1], az);
            an = ffma2(hv.y, Wn2[2*i+1], an);
        }
        float arf = __uint_as_float((uint32_t)ar) + __uint_as_float((uint32_t)(ar >> 32));
        float azf = __uint_as_float((uint32_t)az) + __uint_as_float((uint32_t)(az >> 32));
        float anf = __uint_as_float((uint32_t)an) + __uint_as_float((uint32_t)(an >> 32));

        float r = sigmoid_fast(xr + arf);
        float z = sigmoid_fast(xz + azf);
        float n = tanh_fast(fmaf(r, anf, xn));
        h = fmaf(z, h - n, n);

        sh[wid][(t + 1) & 1][j] = h;
        __syncwarp();
    }

    float v = h * W_head[j];
    #pragma unroll
    for (int o = 16; o > 0; o >>= 1)
        v += __shfl_xor_sync(0xffffffffu, v, o);
    if (j == 0)
        out[row] = sigmoid_fast(v + b_head[0]);
}

extern "C" void kernel_launch(void* const* d_in, const int* in_sizes, int n_in,
                              void* d_out, int out_size)
{
    const float* x      = (const float*)d_in[0];
    const float* W_ih   = (const float*)d_in[1];
    const float* W_hh   = (const float*)d_in[2];
    const float* b_ih   = (const float*)d_in[3];
    const float* b_hh   = (const float*)d_in[4];
    const float* W_head = (const float*)d_in[5];
    const float* b_head = (const float*)d_in[6];
    float* out = (float*)d_out;

    float* xg;
    cudaGetSymbolAddress((void**)&xg, g_xg);

    cudaFuncSetAttribute(proj_kernel, cudaFuncAttributeMaxDynamicSharedMemorySize, SMEM_P1);
    proj_kernel<<<(B_ * T_) / PM, 256, SMEM_P1>>>(x, W_ih, b_ih, xg);
    gru_kernel<<<B_ / WARPS_P2, 32 * WARPS_P2>>>(xg, W_hh, b_hh, W_head, b_head, out);
}